// round 3
// baseline (speedup 1.0000x reference)
#include <cuda_runtime.h>
#include <cstdint>

#define B_ 4
#define N_ 2048
#define M_ 2048
#define C_ 1024
#define H_ 16
#define D_ 64
#define SCALE_ 0.125f

// Scratch (allocation-free rule: __device__ globals)
__device__ float g_q[(size_t)B_ * H_ * N_ * D_];   // (B,H,N,D)
__device__ float g_k[(size_t)B_ * H_ * M_ * D_];   // (B,H,M,D)
__device__ float g_v[(size_t)B_ * H_ * M_ * D_];   // (B,H,M,D)
__device__ float g_x[(size_t)B_ * N_ * C_];        // (B,N,C) attention output

// ---------------------------------------------------------------------------
// helpers
// ---------------------------------------------------------------------------
__device__ __forceinline__ uint32_t f2tf(float x) {
    uint32_t u;
    asm("cvt.rna.tf32.f32 %0, %1;" : "=r"(u) : "f"(x));
    return u;
}

__device__ __forceinline__ void mma8(float c[4],
                                     uint32_t a0, uint32_t a1, uint32_t a2, uint32_t a3,
                                     uint32_t b0, uint32_t b1) {
    asm volatile(
        "mma.sync.aligned.m16n8k8.row.col.f32.tf32.tf32.f32 "
        "{%0,%1,%2,%3},{%4,%5,%6,%7},{%8,%9},{%0,%1,%2,%3};"
        : "+f"(c[0]), "+f"(c[1]), "+f"(c[2]), "+f"(c[3])
        : "r"(a0), "r"(a1), "r"(a2), "r"(a3), "r"(b0), "r"(b1));
}

__device__ __forceinline__ uint32_t smem_u32(const void* p) {
    return (uint32_t)__cvta_generic_to_shared(p);
}
#define CP16(dst, src) asm volatile("cp.async.cg.shared.global [%0], [%1], 16;" :: "r"(dst), "l"(src))
#define CP_COMMIT()    asm volatile("cp.async.commit_group;")
#define CP_WAIT0()     asm volatile("cp.async.wait_group 0;")

// ---------------------------------------------------------------------------
// 128x128 tf32 GEMM tile (NT): out[r][c] = sum_k X[r][k] * W[c][k]
// 512 threads / 16 warps (4m x 4n), warp tile 32x32. BK=16, cp.async
// double-buffered smem (raw f32, stride 20 => conflict-free), cvt at load.
// One __syncthreads per K-step.
// ---------------------------------------------------------------------------
#define GSTRIDE 20
#define GSTAGE  (128 * GSTRIDE)

__device__ __forceinline__ void gemm_tile(const float* __restrict__ X,
                                          const float* __restrict__ W,
                                          int row0, int col0, float c[2][4][4]) {
    __shared__ float As[2][GSTAGE];
    __shared__ float Bs[2][GSTAGE];
    const int tid  = threadIdx.x;
    const int lane = tid & 31;
    const int g    = lane >> 2, tg = lane & 3;
    const int wid  = tid >> 5;
    const int wm   = (wid & 3) * 32;
    const int wn   = (wid >> 2) * 32;

    const int r  = tid >> 2;        // 0..127
    const int c4 = tid & 3;         // 0..3 (float4 chunk within 16-float slab)

    const float* asrc = X + (size_t)(row0 + r) * C_ + c4 * 4;
    const float* bsrc = W + (size_t)(col0 + r) * C_ + c4 * 4;
    const uint32_t adst0 = smem_u32(&As[0][r * GSTRIDE + c4 * 4]);
    const uint32_t bdst0 = smem_u32(&Bs[0][r * GSTRIDE + c4 * 4]);

    // prologue: stage 0
    CP16(adst0, asrc);
    CP16(bdst0, bsrc);
    CP_COMMIT();

    for (int kt = 0; kt < C_ / 16; ++kt) {
        CP_WAIT0();
        __syncthreads();
        if (kt + 1 < C_ / 16) {
            uint32_t off = ((kt + 1) & 1) * (GSTAGE * 4);
            CP16(adst0 + off, asrc + (kt + 1) * 16);
            CP16(bdst0 + off, bsrc + (kt + 1) * 16);
            CP_COMMIT();
        }
        const float* A = As[kt & 1];
        const float* Bb = Bs[kt & 1];
        #pragma unroll
        for (int kk = 0; kk < 2; ++kk) {
            uint32_t a[2][4];
            #pragma unroll
            for (int mt = 0; mt < 2; ++mt) {
                int ab = (wm + mt * 16 + g) * GSTRIDE + kk * 8 + tg;
                a[mt][0] = f2tf(A[ab]);
                a[mt][1] = f2tf(A[ab + 8 * GSTRIDE]);
                a[mt][2] = f2tf(A[ab + 4]);
                a[mt][3] = f2tf(A[ab + 8 * GSTRIDE + 4]);
            }
            uint32_t b[4][2];
            #pragma unroll
            for (int nt = 0; nt < 4; ++nt) {
                int bb = (wn + nt * 8 + g) * GSTRIDE + kk * 8 + tg;
                b[nt][0] = f2tf(Bb[bb]);
                b[nt][1] = f2tf(Bb[bb + 4]);
            }
            #pragma unroll
            for (int mt = 0; mt < 2; ++mt)
                #pragma unroll
                for (int nt = 0; nt < 4; ++nt)
                    mma8(c[mt][nt], a[mt][0], a[mt][1], a[mt][2], a[mt][3],
                         b[nt][0], b[nt][1]);
        }
    }
}

// ---------------------------------------------------------------------------
// QKV projections (z = 0/1/2 -> q/k/v), output scattered to (B,H,S,D)
// ---------------------------------------------------------------------------
__global__ void __launch_bounds__(512, 2) proj_qkv_kernel(
    const float* __restrict__ q_in, const float* __restrict__ k_in,
    const float* __restrict__ v_in, const float* __restrict__ Wq,
    const float* __restrict__ Wk, const float* __restrict__ Wv) {
    const float* X; const float* W; float* O;
    if (blockIdx.z == 0)      { X = q_in; W = Wq; O = g_q; }
    else if (blockIdx.z == 1) { X = k_in; W = Wk; O = g_k; }
    else                      { X = v_in; W = Wv; O = g_v; }

    const int row0 = blockIdx.y * 128;
    const int col0 = blockIdx.x * 128;

    float c[2][4][4];
    #pragma unroll
    for (int mt = 0; mt < 2; ++mt)
        #pragma unroll
        for (int nt = 0; nt < 4; ++nt)
            #pragma unroll
            for (int j = 0; j < 4; ++j) c[mt][nt][j] = 0.f;

    gemm_tile(X, W, row0, col0, c);

    const int lane = threadIdx.x & 31, wid = threadIdx.x >> 5;
    const int g = lane >> 2, tg = lane & 3;
    const int wm = (wid & 3) * 32, wn = (wid >> 2) * 32;

    #pragma unroll
    for (int mt = 0; mt < 2; ++mt)
        #pragma unroll
        for (int half = 0; half < 2; ++half) {
            int r = row0 + wm + mt * 16 + g + half * 8;
            int b = r >> 11, s = r & 2047;
            #pragma unroll
            for (int nt = 0; nt < 4; ++nt) {
                int col = col0 + wn + nt * 8 + 2 * tg;
                int h = col >> 6, d0 = col & 63;
                *(float2*)&O[((size_t)(b * H_ + h) * N_ + s) * D_ + d0] =
                    make_float2(c[mt][nt][half * 2], c[mt][nt][half * 2 + 1]);
            }
        }
}

// ---------------------------------------------------------------------------
// Output projection + bias -> d_out (B,N,C)
// ---------------------------------------------------------------------------
__global__ void __launch_bounds__(512, 2) proj_out_kernel(
    const float* __restrict__ Wp, const float* __restrict__ bp,
    float* __restrict__ out) {
    const int row0 = blockIdx.y * 128;
    const int col0 = blockIdx.x * 128;

    float c[2][4][4];
    #pragma unroll
    for (int mt = 0; mt < 2; ++mt)
        #pragma unroll
        for (int nt = 0; nt < 4; ++nt)
            #pragma unroll
            for (int j = 0; j < 4; ++j) c[mt][nt][j] = 0.f;

    gemm_tile(g_x, Wp, row0, col0, c);

    const int lane = threadIdx.x & 31, wid = threadIdx.x >> 5;
    const int g = lane >> 2, tg = lane & 3;
    const int wm = (wid & 3) * 32, wn = (wid >> 2) * 32;

    #pragma unroll
    for (int mt = 0; mt < 2; ++mt)
        #pragma unroll
        for (int half = 0; half < 2; ++half) {
            int r = row0 + wm + mt * 16 + g + half * 8;
            #pragma unroll
            for (int nt = 0; nt < 4; ++nt) {
                int col = col0 + wn + nt * 8 + 2 * tg;
                float2 bias = *(const float2*)&bp[col];
                *(float2*)&out[(size_t)r * C_ + col] =
                    make_float2(c[mt][nt][half * 2] + bias.x,
                                c[mt][nt][half * 2 + 1] + bias.y);
            }
        }
}

// ---------------------------------------------------------------------------
// Flash attention, tf32 mma, cp.async double-buffered K/V.
// 128 threads / 4 warps; block = 64 query rows of one (b,h); key tile = 32.
// Q fragments live in registers (loaded once via an smem staging pass that
// reuses the K buffers). P has its own buffer. 2 __syncthreads per tile.
// smem: Kb[2][32*68] f32 raw | Vb[2][32*72] f32 raw | Pb[64*36] tf32 = 45056 B
// ---------------------------------------------------------------------------
__global__ void __launch_bounds__(128, 3) flash_kernel() {
    __shared__ float    Kb[2][32 * 68];
    __shared__ float    Vb[2][32 * 72];
    __shared__ uint32_t Pb[64 * 36];

    const int tid  = threadIdx.x;
    const int lane = tid & 31, w = tid >> 5;
    const int g    = lane >> 2, tg = lane & 3;
    const int bh   = blockIdx.y;
    const int n0   = blockIdx.x * 64;

    const float* qb = g_q + (size_t)bh * N_ * D_ + (size_t)n0 * D_;
    const float* kb = g_k + (size_t)bh * M_ * D_;
    const float* vb = g_v + (size_t)bh * M_ * D_;

    // ---- stage Q (64x64 f32, stride 68) into the K double-buffer region ----
    float* Qs = &Kb[0][0];            // 2*2176 = 4352 floats = 64*68 exactly
    #pragma unroll
    for (int j = 0; j < 8; ++j) {
        int idx = tid + j * 128;
        int r = idx >> 4, c4 = idx & 15;
        CP16(smem_u32(&Qs[r * 68 + c4 * 4]), qb + r * 64 + c4 * 4);
    }
    CP_COMMIT();
    CP_WAIT0();
    __syncthreads();

    // ---- extract Q fragments (scaled, tf32) into registers ----
    uint32_t qf[8][4];
    #pragma unroll
    for (int kk = 0; kk < 8; ++kk) {
        int ab = (w * 16 + g) * 68 + kk * 8 + tg;
        qf[kk][0] = f2tf(Qs[ab] * SCALE_);
        qf[kk][1] = f2tf(Qs[ab + 8 * 68] * SCALE_);
        qf[kk][2] = f2tf(Qs[ab + 4] * SCALE_);
        qf[kk][3] = f2tf(Qs[ab + 8 * 68 + 4] * SCALE_);
    }
    __syncthreads();   // Q staging fully read before K overwrites it

    float o[8][4];
    float mrow[2], lrow[2];
    #pragma unroll
    for (int nt = 0; nt < 8; ++nt)
        #pragma unroll
        for (int j = 0; j < 4; ++j) o[nt][j] = 0.f;
    mrow[0] = mrow[1] = -1e30f;
    lrow[0] = lrow[1] = 0.f;

    const int rKV = tid >> 2;       // unused pattern below uses idx loop
    (void)rKV;

    // issue K/V tile 0
    {
        #pragma unroll
        for (int j = 0; j < 2; ++j) {
            int idx = tid + j * 128;            // 256 chunks of 16B per array
            int r = idx >> 3, c4 = idx & 7;     // 32 rows x 8 float4
            CP16(smem_u32(&Kb[0][r * 68 + c4 * 8]), kb + r * 64 + c4 * 8);
            CP16(smem_u32(&Kb[0][r * 68 + c4 * 8 + 4]), kb + r * 64 + c4 * 8 + 4);
            CP16(smem_u32(&Vb[0][r * 72 + c4 * 8]), vb + r * 64 + c4 * 8);
            CP16(smem_u32(&Vb[0][r * 72 + c4 * 8 + 4]), vb + r * 64 + c4 * 8 + 4);
        }
        CP_COMMIT();
    }

    for (int t = 0; t < M_ / 32; ++t) {
        CP_WAIT0();
        __syncthreads();
        if (t + 1 < M_ / 32) {
            int buf = (t + 1) & 1;
            const float* ks = kb + (size_t)(t + 1) * 32 * 64;
            const float* vs = vb + (size_t)(t + 1) * 32 * 64;
            #pragma unroll
            for (int j = 0; j < 2; ++j) {
                int idx = tid + j * 128;
                int r = idx >> 3, c4 = idx & 7;
                CP16(smem_u32(&Kb[buf][r * 68 + c4 * 8]), ks + r * 64 + c4 * 8);
                CP16(smem_u32(&Kb[buf][r * 68 + c4 * 8 + 4]), ks + r * 64 + c4 * 8 + 4);
                CP16(smem_u32(&Vb[buf][r * 72 + c4 * 8]), vs + r * 64 + c4 * 8);
                CP16(smem_u32(&Vb[buf][r * 72 + c4 * 8 + 4]), vs + r * 64 + c4 * 8 + 4);
            }
            CP_COMMIT();
        }
        const float* K = Kb[t & 1];
        const float* V = Vb[t & 1];

        // ---- S = (Q*SCALE) K^T : m16 x n32 x k64 per warp ----
        float s[4][4];
        #pragma unroll
        for (int nt = 0; nt < 4; ++nt)
            #pragma unroll
            for (int j = 0; j < 4; ++j) s[nt][j] = 0.f;

        #pragma unroll
        for (int kk = 0; kk < 8; ++kk) {
            #pragma unroll
            for (int nt = 0; nt < 4; ++nt) {
                int bb = (nt * 8 + g) * 68 + kk * 8 + tg;
                mma8(s[nt], qf[kk][0], qf[kk][1], qf[kk][2], qf[kk][3],
                     f2tf(K[bb]), f2tf(K[bb + 4]));
            }
        }

        // ---- online softmax (reduce over tg lanes) ----
        #pragma unroll
        for (int r = 0; r < 2; ++r) {
            float mt_ = s[0][2 * r];
            #pragma unroll
            for (int nt = 0; nt < 4; ++nt) {
                mt_ = fmaxf(mt_, s[nt][2 * r]);
                mt_ = fmaxf(mt_, s[nt][2 * r + 1]);
            }
            mt_ = fmaxf(mt_, __shfl_xor_sync(0xffffffffu, mt_, 1));
            mt_ = fmaxf(mt_, __shfl_xor_sync(0xffffffffu, mt_, 2));
            float mn = fmaxf(mrow[r], mt_);
            float alpha = __expf(mrow[r] - mn);
            mrow[r] = mn;
            float rs = 0.f;
            #pragma unroll
            for (int nt = 0; nt < 4; ++nt) {
                s[nt][2 * r]     = __expf(s[nt][2 * r] - mn);
                s[nt][2 * r + 1] = __expf(s[nt][2 * r + 1] - mn);
                rs += s[nt][2 * r] + s[nt][2 * r + 1];
            }
            rs += __shfl_xor_sync(0xffffffffu, rs, 1);
            rs += __shfl_xor_sync(0xffffffffu, rs, 2);
            lrow[r] = lrow[r] * alpha + rs;
            #pragma unroll
            for (int nt = 0; nt < 8; ++nt) {
                o[nt][2 * r]     *= alpha;
                o[nt][2 * r + 1] *= alpha;
            }
        }

        // ---- store P tile [64][36] (tf32) ----
        #pragma unroll
        for (int r = 0; r < 2; ++r) {
            int prow = w * 16 + g + 8 * r;
            #pragma unroll
            for (int nt = 0; nt < 4; ++nt)
                *(uint2*)&Pb[prow * 36 + nt * 8 + 2 * tg] =
                    make_uint2(f2tf(s[nt][2 * r]), f2tf(s[nt][2 * r + 1]));
        }
        __syncthreads();

        // ---- O += P V : m16 x n64 x k32 per warp ----
        #pragma unroll
        for (int kk = 0; kk < 4; ++kk) {
            int ab = (w * 16 + g) * 36 + kk * 8 + tg;
            uint32_t a0 = Pb[ab], a1 = Pb[ab + 8 * 36];
            uint32_t a2 = Pb[ab + 4], a3 = Pb[ab + 8 * 36 + 4];
            #pragma unroll
            for (int nt = 0; nt < 8; ++nt) {
                uint32_t b0 = f2tf(V[(kk * 8 + tg) * 72 + nt * 8 + g]);
                uint32_t b1 = f2tf(V[(kk * 8 + tg + 4) * 72 + nt * 8 + g]);
                mma8(o[nt], a0, a1, a2, a3, b0, b1);
            }
        }
        // next-iteration top __syncthreads orders PV reads vs new P/K/V writes
    }

    // ---- normalize + write (B,N,C) ----
    const int b = bh >> 4, h = bh & 15;
    #pragma unroll
    for (int r = 0; r < 2; ++r) {
        float inv = 1.0f / lrow[r];
        int qrow = n0 + w * 16 + g + 8 * r;
        #pragma unroll
        for (int nt = 0; nt < 8; ++nt) {
            *(float2*)&g_x[(size_t)(b * N_ + qrow) * C_ + h * 64 + nt * 8 + 2 * tg] =
                make_float2(o[nt][2 * r] * inv, o[nt][2 * r + 1] * inv);
        }
    }
}

// ---------------------------------------------------------------------------
extern "C" void kernel_launch(void* const* d_in, const int* in_sizes, int n_in,
                              void* d_out, int out_size) {
    const float* query = (const float*)d_in[0];
    const float* key   = (const float*)d_in[1];
    const float* value = (const float*)d_in[2];
    const float* Wq    = (const float*)d_in[3];
    const float* Wk    = (const float*)d_in[4];
    const float* Wv    = (const float*)d_in[5];
    const float* Wp    = (const float*)d_in[6];
    const float* bp    = (const float*)d_in[7];
    float* out = (float*)d_out;

    dim3 gqkv(C_ / 128, (B_ * N_) / 128, 3);
    proj_qkv_kernel<<<gqkv, 512>>>(query, key, value, Wq, Wk, Wv);

    dim3 gfl(N_ / 64, B_ * H_);
    flash_kernel<<<gfl, 128>>>();

    dim3 gout(C_ / 128, (B_ * N_) / 128);
    proj_out_kernel<<<gout, 512>>>(Wp, bp, out);
}